// round 1
// baseline (speedup 1.0000x reference)
#include <cuda_runtime.h>
#include <math.h>

#define NN   100000
#define EE_MAX 3400000     // capacity for E + N self loops
#define HD   16
#define FIN  767
#define NC   10

// ---------------- scratch (static device globals; no allocations) ----------
__device__ float g_h  [NN * HD];   // relu(x W1^T + b)
__device__ float g_hn [NN * HD];   // normalized h
__device__ float g_x1n[NN * HD];   // normalized x1
__device__ float g_h2 [NN * HD];   // conv2 output
__device__ int   g_deg [NN];
__device__ int   g_rowptr[NN + 1];
__device__ int   g_cursor[NN];
__device__ int   g_csrc[EE_MAX];
__device__ int   g_aux[256];

// ---------------- CSR build ------------------------------------------------
__global__ void k_deg_init(int n) {
    int i = blockIdx.x * blockDim.x + threadIdx.x;
    if (i < n) g_deg[i] = 1;                 // self loop
}

__global__ void k_count(const int* __restrict__ ei, int E) {
    int e = blockIdx.x * blockDim.x + threadIdx.x;
    if (e < E) atomicAdd(&g_deg[ei[E + e]], 1);   // dst row
}

// inclusive scan of g_deg into g_rowptr[1..n], chunk totals to g_aux
__global__ void k_scan_chunk(int n) {
    __shared__ int sh[1024];
    int tid = threadIdx.x;
    int gid = blockIdx.x * 1024 + tid;
    int v = (gid < n) ? g_deg[gid] : 0;
    sh[tid] = v;
    __syncthreads();
    for (int off = 1; off < 1024; off <<= 1) {
        int t = (tid >= off) ? sh[tid - off] : 0;
        __syncthreads();
        sh[tid] += t;
        __syncthreads();
    }
    if (gid < n) g_rowptr[gid + 1] = sh[tid];
    if (tid == 1023) g_aux[blockIdx.x] = sh[1023];
}

__global__ void k_scan_aux(int nb) {
    if (threadIdx.x == 0 && blockIdx.x == 0) {
        int run = 0;
        for (int b = 0; b < nb; b++) { int t = g_aux[b]; g_aux[b] = run; run += t; }
    }
}

__global__ void k_scan_add(int n) {
    int gid = blockIdx.x * 1024 + threadIdx.x;
    if (gid < n) g_rowptr[gid + 1] += g_aux[blockIdx.x];
    if (gid == 0) g_rowptr[0] = 0;
}

__global__ void k_cursor_init(int n) {
    int i = blockIdx.x * blockDim.x + threadIdx.x;
    if (i < n) g_cursor[i] = g_rowptr[i];
}

__global__ void k_scatter(const int* __restrict__ ei, int E, int n) {
    int idx = blockIdx.x * blockDim.x + threadIdx.x;
    int total = E + n;
    if (idx >= total) return;
    int src, dst;
    if (idx < E) { src = ei[idx]; dst = ei[E + idx]; }
    else         { src = idx - E; dst = src; }
    int pos = atomicAdd(&g_cursor[dst], 1);
    g_csrc[pos] = src;
}

// ---------------- lin1 + relu + row-normalize ------------------------------
// warp per 4 rows; W1 staged in smem; 64 accumulators per lane, butterfly reduce.
__global__ __launch_bounds__(256) void k_lin1(const float* __restrict__ x,
                                              const float* __restrict__ w,
                                              const float* __restrict__ b,
                                              int n) {
    __shared__ float ws[HD * FIN];
    for (int i = threadIdx.x; i < HD * FIN; i += blockDim.x) ws[i] = w[i];
    __syncthreads();

    int warp = threadIdx.x >> 5, lane = threadIdx.x & 31;
    int rowBase = (blockIdx.x * 8 + warp) * 4;
    if (rowBase >= n) return;

    float acc[4][16];
#pragma unroll
    for (int r = 0; r < 4; r++)
#pragma unroll
        for (int k = 0; k < 16; k++) acc[r][k] = 0.f;

    const float* x0 = x + (size_t)rowBase * FIN;
    for (int j = lane; j < FIN; j += 32) {
        float xv0 = x0[j];
        float xv1 = x0[FIN + j];
        float xv2 = x0[2 * FIN + j];
        float xv3 = x0[3 * FIN + j];
#pragma unroll
        for (int k = 0; k < 16; k++) {
            float wv = ws[k * FIN + j];
            acc[0][k] += xv0 * wv;
            acc[1][k] += xv1 * wv;
            acc[2][k] += xv2 * wv;
            acc[3][k] += xv3 * wv;
        }
    }
#pragma unroll
    for (int off = 16; off; off >>= 1)
#pragma unroll
        for (int r = 0; r < 4; r++)
#pragma unroll
            for (int k = 0; k < 16; k++)
                acc[r][k] += __shfl_xor_sync(0xffffffffu, acc[r][k], off);

    if (lane == 0) {
#pragma unroll
        for (int r = 0; r < 4; r++) {
            float hv[16];
            float ss = 0.f;
#pragma unroll
            for (int k = 0; k < 16; k++) {
                float t = acc[r][k] + __ldg(b + k);
                t = fmaxf(t, 0.f);
                hv[k] = t;
                ss += t * t;
            }
            float inv = 1.f / fmaxf(sqrtf(ss), 1e-12f);
            size_t row = (size_t)(rowBase + r) * HD;
            float4* H  = (float4*)(g_h  + row);
            float4* HN = (float4*)(g_hn + row);
#pragma unroll
            for (int q = 0; q < 4; q++) {
                H[q]  = make_float4(hv[4*q], hv[4*q+1], hv[4*q+2], hv[4*q+3]);
                HN[q] = make_float4(hv[4*q]*inv, hv[4*q+1]*inv, hv[4*q+2]*inv, hv[4*q+3]*inv);
            }
        }
    }
}

// ---------------- row normalize (for x1) -----------------------------------
__global__ void k_norm16(const float* __restrict__ in, float* __restrict__ outn, int n) {
    int i = blockIdx.x * blockDim.x + threadIdx.x;
    if (i >= n) return;
    const float4* v4 = (const float4*)(in + (size_t)i * HD);
    float4 a0 = v4[0], a1 = v4[1], a2 = v4[2], a3 = v4[3];
    float ss = a0.x*a0.x + a0.y*a0.y + a0.z*a0.z + a0.w*a0.w
             + a1.x*a1.x + a1.y*a1.y + a1.z*a1.z + a1.w*a1.w
             + a2.x*a2.x + a2.y*a2.y + a2.z*a2.z + a2.w*a2.w
             + a3.x*a3.x + a3.y*a3.y + a3.z*a3.z + a3.w*a3.w;
    float inv = 1.f / fmaxf(sqrtf(ss), 1e-12f);
    float4* o4 = (float4*)(outn + (size_t)i * HD);
    o4[0] = make_float4(a0.x*inv, a0.y*inv, a0.z*inv, a0.w*inv);
    o4[1] = make_float4(a1.x*inv, a1.y*inv, a1.z*inv, a1.w*inv);
    o4[2] = make_float4(a2.x*inv, a2.y*inv, a2.z*inv, a2.w*inv);
    o4[3] = make_float4(a3.x*inv, a3.y*inv, a3.z*inv, a3.w*inv);
}

// ---------------- AGNN conv: warp per node, single-pass online softmax -----
__global__ __launch_bounds__(256) void k_conv(const float* __restrict__ feat,
                                              const float* __restrict__ featn,
                                              const float* __restrict__ beta_ptr,
                                              float beta_const,
                                              float* __restrict__ out, int n) {
    int gw   = (blockIdx.x * blockDim.x + threadIdx.x) >> 5;
    int lane = threadIdx.x & 31;
    if (gw >= n) return;
    float beta = beta_ptr ? __ldg(beta_ptr) : beta_const;

    const float4* fn4 = (const float4*)featn;
    const float4* f4  = (const float4*)feat;
    float4 q0 = fn4[gw*4+0], q1 = fn4[gw*4+1], q2 = fn4[gw*4+2], q3 = fn4[gw*4+3];

    int start = g_rowptr[gw], end = g_rowptr[gw + 1];

    float m = -INFINITY, ssum = 0.f;
    float acc[16];
#pragma unroll
    for (int k = 0; k < 16; k++) acc[k] = 0.f;

    for (int e = start + lane; e < end; e += 32) {
        int s = g_csrc[e];
        float4 a0 = fn4[s*4+0], a1 = fn4[s*4+1], a2 = fn4[s*4+2], a3 = fn4[s*4+3];
        float dot = a0.x*q0.x + a0.y*q0.y + a0.z*q0.z + a0.w*q0.w
                  + a1.x*q1.x + a1.y*q1.y + a1.z*q1.z + a1.w*q1.w
                  + a2.x*q2.x + a2.y*q2.y + a2.z*q2.z + a2.w*q2.w
                  + a3.x*q3.x + a3.y*q3.y + a3.z*q3.z + a3.w*q3.w;
        float a = beta * dot;
        float mn = fmaxf(m, a);
        float scale = __expf(m - mn);   // 0 on first edge (m=-inf)
        float wgt   = __expf(a - mn);
        ssum = ssum * scale + wgt;
        float4 b0 = f4[s*4+0], b1 = f4[s*4+1], b2 = f4[s*4+2], b3 = f4[s*4+3];
        acc[0]  = acc[0] *scale + wgt*b0.x;  acc[1]  = acc[1] *scale + wgt*b0.y;
        acc[2]  = acc[2] *scale + wgt*b0.z;  acc[3]  = acc[3] *scale + wgt*b0.w;
        acc[4]  = acc[4] *scale + wgt*b1.x;  acc[5]  = acc[5] *scale + wgt*b1.y;
        acc[6]  = acc[6] *scale + wgt*b1.z;  acc[7]  = acc[7] *scale + wgt*b1.w;
        acc[8]  = acc[8] *scale + wgt*b2.x;  acc[9]  = acc[9] *scale + wgt*b2.y;
        acc[10] = acc[10]*scale + wgt*b2.z;  acc[11] = acc[11]*scale + wgt*b2.w;
        acc[12] = acc[12]*scale + wgt*b3.x;  acc[13] = acc[13]*scale + wgt*b3.y;
        acc[14] = acc[14]*scale + wgt*b3.z;  acc[15] = acc[15]*scale + wgt*b3.w;
        m = mn;
    }

    // merge lanes: rescale to global max, then sum-reduce
    float M = m;
#pragma unroll
    for (int off = 16; off; off >>= 1) M = fmaxf(M, __shfl_xor_sync(0xffffffffu, M, off));
    float sc = __expf(m - M);           // 0 for lanes with no edges
    ssum *= sc;
#pragma unroll
    for (int k = 0; k < 16; k++) acc[k] *= sc;
#pragma unroll
    for (int off = 16; off; off >>= 1) {
        ssum += __shfl_xor_sync(0xffffffffu, ssum, off);
#pragma unroll
        for (int k = 0; k < 16; k++)
            acc[k] += __shfl_xor_sync(0xffffffffu, acc[k], off);
    }

    if (lane == 0) {
        float inv = 1.f / ssum;
        float4* o4 = (float4*)(out + (size_t)gw * HD);
        o4[0] = make_float4(acc[0]*inv,  acc[1]*inv,  acc[2]*inv,  acc[3]*inv);
        o4[1] = make_float4(acc[4]*inv,  acc[5]*inv,  acc[6]*inv,  acc[7]*inv);
        o4[2] = make_float4(acc[8]*inv,  acc[9]*inv,  acc[10]*inv, acc[11]*inv);
        o4[3] = make_float4(acc[12]*inv, acc[13]*inv, acc[14]*inv, acc[15]*inv);
    }
}

// ---------------- lin2 + log_softmax ---------------------------------------
__global__ void k_lin2(const float* __restrict__ w2, const float* __restrict__ b2,
                       float* __restrict__ out, int n) {
    __shared__ float ws[NC * HD];
    __shared__ float bs[NC];
    if (threadIdx.x < NC * HD) ws[threadIdx.x] = w2[threadIdx.x];
    if (threadIdx.x < NC)      bs[threadIdx.x] = b2[threadIdx.x];
    __syncthreads();
    int i = blockIdx.x * blockDim.x + threadIdx.x;
    if (i >= n) return;
    const float4* v4 = (const float4*)(g_h2 + (size_t)i * HD);
    float v[16];
    float4 t0 = v4[0], t1 = v4[1], t2 = v4[2], t3 = v4[3];
    v[0]=t0.x; v[1]=t0.y; v[2]=t0.z; v[3]=t0.w;
    v[4]=t1.x; v[5]=t1.y; v[6]=t1.z; v[7]=t1.w;
    v[8]=t2.x; v[9]=t2.y; v[10]=t2.z; v[11]=t2.w;
    v[12]=t3.x; v[13]=t3.y; v[14]=t3.z; v[15]=t3.w;
    float z[NC];
#pragma unroll
    for (int c = 0; c < NC; c++) {
        float s = bs[c];
#pragma unroll
        for (int k = 0; k < 16; k++) s += v[k] * ws[c * 16 + k];
        z[c] = s;
    }
    float mx = z[0];
#pragma unroll
    for (int c = 1; c < NC; c++) mx = fmaxf(mx, z[c]);
    float se = 0.f;
#pragma unroll
    for (int c = 0; c < NC; c++) se += __expf(z[c] - mx);
    float lse = mx + __logf(se);
#pragma unroll
    for (int c = 0; c < NC; c++) out[(size_t)i * NC + c] = z[c] - lse;
}

// ---------------- launch ---------------------------------------------------
extern "C" void kernel_launch(void* const* d_in, const int* in_sizes, int n_in,
                              void* d_out, int out_size) {
    const float* x    = (const float*)d_in[0];
    const int*   ei   = (const int*)  d_in[1];
    const float* w1   = (const float*)d_in[2];
    const float* b1   = (const float*)d_in[3];
    const float* bet2 = (const float*)d_in[4];
    const float* w2   = (const float*)d_in[5];
    const float* b2   = (const float*)d_in[6];
    float* out = (float*)d_out;

    int n = NN;
    int E = in_sizes[1] / 2;

    float* x1 = out + (size_t)n * NC;   // x1 output lives in d_out

    float* p_h;  cudaGetSymbolAddress((void**)&p_h,  g_h);
    float* p_hn; cudaGetSymbolAddress((void**)&p_hn, g_hn);
    float* p_x1n;cudaGetSymbolAddress((void**)&p_x1n,g_x1n);
    float* p_h2; cudaGetSymbolAddress((void**)&p_h2, g_h2);

    const int T = 256;
    // CSR build
    k_deg_init<<<(n + T - 1) / T, T>>>(n);
    k_count<<<(E + T - 1) / T, T>>>(ei, E);
    int nchunk = (n + 1023) / 1024;
    k_scan_chunk<<<nchunk, 1024>>>(n);
    k_scan_aux<<<1, 32>>>(nchunk);
    k_scan_add<<<nchunk, 1024>>>(n);
    k_cursor_init<<<(n + T - 1) / T, T>>>(n);
    k_scatter<<<(E + n + T - 1) / T, T>>>(ei, E, n);

    // MLP front
    k_lin1<<<(n / 4 + 7) / 8, 256>>>(x, w1, b1, n);

    // conv1 (beta = 1) -> x1 (directly into d_out tail)
    k_conv<<<(n + 7) / 8, 256>>>(p_h, p_hn, nullptr, 1.0f, x1, n);

    // normalize x1, conv2 (beta = beta2)
    k_norm16<<<(n + T - 1) / T, T>>>(x1, p_x1n, n);
    k_conv<<<(n + 7) / 8, 256>>>(x1, p_x1n, bet2, 1.0f, p_h2, n);

    // classifier + log_softmax
    k_lin2<<<(n + T - 1) / T, T>>>(w2, b2, out, n);
}

// round 2
// speedup vs baseline: 1.2996x; 1.2996x over previous
#include <cuda_runtime.h>
#include <math.h>

#define NN     100000
#define EE_MAX 3400000
#define HD     16
#define FIN    767
#define NC     10
#define EPSV   1e-12f

// ---------------- scratch ---------------------------------------------------
__device__ float g_hn  [NN * HD];   // normalized h
__device__ float g_nrm1[NN];        // max(||h||, eps)
__device__ float g_x1n [NN * HD];   // normalized x1
__device__ float g_nrm2[NN];        // max(||x1||, eps)
__device__ float g_h2  [NN * HD];   // conv2 output
__device__ int   g_deg [NN];
__device__ int   g_rowptr[NN + 1];
__device__ int   g_cursor[NN];
__device__ int   g_csrc[EE_MAX];
__device__ int   g_aux[256];

// ---------------- f32x2 helpers ---------------------------------------------
__device__ __forceinline__ unsigned long long pk2(float lo, float hi) {
    unsigned long long r;
    asm("mov.b64 %0, {%1,%2};" : "=l"(r) : "f"(lo), "f"(hi));
    return r;
}
__device__ __forceinline__ void upk2(unsigned long long v, float& lo, float& hi) {
    asm("mov.b64 {%0,%1}, %2;" : "=f"(lo), "=f"(hi) : "l"(v));
}
__device__ __forceinline__ unsigned long long ffma2(unsigned long long a,
                                                    unsigned long long b,
                                                    unsigned long long c) {
    unsigned long long d;
    asm("fma.rn.f32x2 %0, %1, %2, %3;" : "=l"(d) : "l"(a), "l"(b), "l"(c));
    return d;
}
__device__ __forceinline__ unsigned long long fadd2(unsigned long long a,
                                                    unsigned long long b) {
    unsigned long long d;
    asm("add.rn.f32x2 %0, %1, %2;" : "=l"(d) : "l"(a), "l"(b));
    return d;
}

// ---------------- CSR build --------------------------------------------------
__global__ void k_deg_init(int n) {
    int i = blockIdx.x * blockDim.x + threadIdx.x;
    if (i < n) g_deg[i] = 1;                 // self loop
}

__global__ void k_count(const int* __restrict__ ei, int E) {
    int e = blockIdx.x * blockDim.x + threadIdx.x;
    if (e < E) atomicAdd(&g_deg[ei[E + e]], 1);
}

__global__ void k_scan_chunk(int n) {
    __shared__ int sh[1024];
    int tid = threadIdx.x;
    int gid = blockIdx.x * 1024 + tid;
    int v = (gid < n) ? g_deg[gid] : 0;
    sh[tid] = v;
    __syncthreads();
    for (int off = 1; off < 1024; off <<= 1) {
        int t = (tid >= off) ? sh[tid - off] : 0;
        __syncthreads();
        sh[tid] += t;
        __syncthreads();
    }
    if (gid < n) g_rowptr[gid + 1] = sh[tid];
    if (tid == 1023) g_aux[blockIdx.x] = sh[1023];
}

// parallel exclusive scan of g_aux (nb <= 128)
__global__ void k_scan_aux(int nb) {
    int tid = threadIdx.x;
    int lane = tid & 31, w = tid >> 5;
    int v = (tid < nb) ? g_aux[tid] : 0;
    int s = v;
#pragma unroll
    for (int off = 1; off < 32; off <<= 1) {
        int t = __shfl_up_sync(0xffffffffu, s, off);
        if (lane >= off) s += t;
    }
    __shared__ int wsum[4];
    if (lane == 31) wsum[w] = s;
    __syncthreads();
    int add = 0;
#pragma unroll
    for (int i = 0; i < 4; i++) add += (i < w) ? wsum[i] : 0;
    if (tid < nb) g_aux[tid] = s - v + add;   // exclusive
}

__global__ void k_scan_add(int n) {
    int gid = blockIdx.x * 1024 + threadIdx.x;
    if (gid < n) g_rowptr[gid + 1] += g_aux[blockIdx.x];
    if (gid == 0) g_rowptr[0] = 0;
}

__global__ void k_cursor_init(int n) {
    int i = blockIdx.x * blockDim.x + threadIdx.x;
    if (i < n) g_cursor[i] = g_rowptr[i];
}

__global__ void k_scatter(const int* __restrict__ ei, int E, int n) {
    int idx = blockIdx.x * blockDim.x + threadIdx.x;
    int total = E + n;
    if (idx >= total) return;
    int src, dst;
    if (idx < E) { src = ei[idx]; dst = ei[E + idx]; }
    else         { src = idx - E; dst = src; }
    int pos = atomicAdd(&g_cursor[dst], 1);
    g_csrc[pos] = src;
}

// ---------------- lin1 + relu + row-normalize (f32x2 packed) -----------------
// warp = 4 rows; lane = j-pair slice; weights staged packed/transposed in smem.
__global__ __launch_bounds__(256) void k_lin1(const float* __restrict__ x,
                                              const float* __restrict__ w,
                                              const float* __restrict__ b,
                                              float* __restrict__ hn,
                                              float* __restrict__ nrm,
                                              int n) {
    // wt2[k][jp] : packed pair (w[k][2jp], w[k][2jp+1]); 16*384*8 = 49152 B
    __shared__ unsigned long long wt2[HD * 384];
    {
        float* wf = (float*)wt2;
        // float layout: wf[k*768 + j] = w[k*767 + j] (j<767), 0 at j=767
        for (int o = threadIdx.x; o < HD * 768; o += 256) {
            int k = o >> 9;          // /768? no! 768 not power of two
            k = o / 768;
            int j = o - k * 768;
            wf[o] = (j < FIN) ? w[k * FIN + j] : 0.f;
        }
    }
    __syncthreads();

    int warp = threadIdx.x >> 5, lane = threadIdx.x & 31;
    int rowBase = (blockIdx.x * 8 + warp) * 4;
    if (rowBase >= n) return;

    unsigned long long acc[64];
#pragma unroll
    for (int i = 0; i < 64; i++) acc[i] = 0ull;

    const float* x0 = x + (size_t)rowBase * FIN;

    // prefetch iteration 0
    unsigned long long xv[4];
    {
        int jj = lane * 2;
#pragma unroll
        for (int r = 0; r < 4; r++) {
            const float* xr = x0 + r * FIN;
            float lo = xr[jj];
            float hi;
            if (jj == 766 && (rowBase + r) == n - 1) hi = 0.f;
            else hi = xr[jj + 1];
            xv[r] = pk2(lo, hi);
        }
    }

    for (int it = 0; it < 12; ++it) {
        int jp = lane + it * 32;
        unsigned long long xnv[4];
        if (it + 1 < 12) {
            int jj = (jp + 32) * 2;
#pragma unroll
            for (int r = 0; r < 4; r++) {
                const float* xr = x0 + r * FIN;
                float lo = xr[jj];
                float hi;
                if (jj == 766 && (rowBase + r) == n - 1) hi = 0.f;
                else hi = xr[jj + 1];
                xnv[r] = pk2(lo, hi);
            }
        }
#pragma unroll
        for (int k = 0; k < HD; k++) {
            unsigned long long wv = wt2[k * 384 + jp];
            acc[0 * 16 + k] = ffma2(xv[0], wv, acc[0 * 16 + k]);
            acc[1 * 16 + k] = ffma2(xv[1], wv, acc[1 * 16 + k]);
            acc[2 * 16 + k] = ffma2(xv[2], wv, acc[2 * 16 + k]);
            acc[3 * 16 + k] = ffma2(xv[3], wv, acc[3 * 16 + k]);
        }
        if (it + 1 < 12) {
#pragma unroll
            for (int r = 0; r < 4; r++) xv[r] = xnv[r];
        }
    }

    // halving butterfly reduce: lane ends owning columns 2*lane, 2*lane+1
#define REDSTEP(OFF, HALF)                                                     \
    {                                                                          \
        bool up = (lane & OFF) != 0;                                           \
        _Pragma("unroll")                                                      \
        for (int i = 0; i < HALF; i++) {                                       \
            unsigned long long send = up ? acc[i] : acc[i + HALF];             \
            unsigned long long recv = __shfl_xor_sync(0xffffffffu, send, OFF); \
            unsigned long long keep = up ? acc[i + HALF] : acc[i];             \
            acc[i] = fadd2(keep, recv);                                        \
        }                                                                      \
    }
    REDSTEP(16, 32)
    REDSTEP(8, 16)
    REDSTEP(4, 8)
    REDSTEP(2, 4)
    REDSTEP(1, 2)
#undef REDSTEP

    // lane owns columns c=2*lane (+1); c = r*16 + k  ->  r = lane>>3, k = (lane&7)*2
    int r  = lane >> 3;
    int kk = (lane & 7) * 2;
    float a0, a1, b0, b1;
    upk2(acc[0], a0, a1);
    upk2(acc[1], b0, b1);
    float h0 = fmaxf(a0 + a1 + __ldg(b + kk),     0.f);
    float h1 = fmaxf(b0 + b1 + __ldg(b + kk + 1), 0.f);
    float ss = h0 * h0 + h1 * h1;
    ss += __shfl_xor_sync(0xffffffffu, ss, 1);
    ss += __shfl_xor_sync(0xffffffffu, ss, 2);
    ss += __shfl_xor_sync(0xffffffffu, ss, 4);
    float nr  = fmaxf(sqrtf(ss), EPSV);
    float inv = 1.f / nr;
    int row = rowBase + r;
    float2 o; o.x = h0 * inv; o.y = h1 * inv;
    *(float2*)(hn + (size_t)row * HD + kk) = o;
    if ((lane & 7) == 0) nrm[row] = nr;
}

// ---------------- normalize x1 -> (featn, nrm) -------------------------------
__global__ void k_norm16(const float* __restrict__ in, float* __restrict__ outn,
                         float* __restrict__ nrm, int n) {
    int i = blockIdx.x * blockDim.x + threadIdx.x;
    if (i >= n) return;
    const float4* v4 = (const float4*)(in + (size_t)i * HD);
    float4 a0 = v4[0], a1 = v4[1], a2 = v4[2], a3 = v4[3];
    float ss = a0.x*a0.x + a0.y*a0.y + a0.z*a0.z + a0.w*a0.w
             + a1.x*a1.x + a1.y*a1.y + a1.z*a1.z + a1.w*a1.w
             + a2.x*a2.x + a2.y*a2.y + a2.z*a2.z + a2.w*a2.w
             + a3.x*a3.x + a3.y*a3.y + a3.z*a3.z + a3.w*a3.w;
    float nr  = fmaxf(sqrtf(ss), EPSV);
    float inv = 1.f / nr;
    nrm[i] = nr;
    float4* o4 = (float4*)(outn + (size_t)i * HD);
    o4[0] = make_float4(a0.x*inv, a0.y*inv, a0.z*inv, a0.w*inv);
    o4[1] = make_float4(a1.x*inv, a1.y*inv, a1.z*inv, a1.w*inv);
    o4[2] = make_float4(a2.x*inv, a2.y*inv, a2.z*inv, a2.w*inv);
    o4[3] = make_float4(a3.x*inv, a3.y*inv, a3.z*inv, a3.w*inv);
}

// ---------------- AGNN conv: warp/node, quad-per-edge coalesced gather -------
// alpha = beta*cos is bounded by |beta| -> fixed-shift softmax, no max pass.
__global__ __launch_bounds__(256) void k_conv(const float* __restrict__ featn,
                                              const float* __restrict__ nrm,
                                              const float* __restrict__ beta_ptr,
                                              float beta_const,
                                              float* __restrict__ out, int n) {
    int gw    = (blockIdx.x * blockDim.x + threadIdx.x) >> 5;
    int lane  = threadIdx.x & 31;
    if (gw >= n) return;
    int chunk = lane & 3;   // which float4 of the 16-float row
    int slot  = lane >> 2;  // which of 8 edges in flight

    float beta = beta_ptr ? __ldg(beta_ptr) : beta_const;
    float ab   = fabsf(beta);

    const float4* fn4 = (const float4*)featn;
    float4 q = fn4[(size_t)gw * 4 + chunk];
    q.x *= beta; q.y *= beta; q.z *= beta; q.w *= beta;

    int start = g_rowptr[gw], end = g_rowptr[gw + 1];
    int nit = (end - start + 7) >> 3;

    float ssum = 0.f;
    float4 acc = make_float4(0.f, 0.f, 0.f, 0.f);

    for (int it = 0; it < nit; ++it) {
        int e = start + slot + it * 8;
        bool valid = (e < end);
        int s = valid ? __ldg(&g_csrc[e]) : __ldg(&g_csrc[start]);
        float4 v = fn4[(size_t)s * 4 + chunk];           // quad-coalesced 64B row
        float d = v.x*q.x + v.y*q.y + v.z*q.z + v.w*q.w; // partial of beta*cos
        d += __shfl_xor_sync(0xffffffffu, d, 1);
        d += __shfl_xor_sync(0xffffffffu, d, 2);
        float ex = valid ? __expf(d - ab) : 0.f;
        float exn = ex * __ldg(&nrm[s]);                 // fold norm into weight
        ssum += ex;
        acc.x += exn * v.x; acc.y += exn * v.y;
        acc.z += exn * v.z; acc.w += exn * v.w;
    }

    // reduce across the 8 slots (same chunk lanes: offsets 4,8,16)
#pragma unroll
    for (int off = 4; off <= 16; off <<= 1) {
        ssum  += __shfl_xor_sync(0xffffffffu, ssum,  off);
        acc.x += __shfl_xor_sync(0xffffffffu, acc.x, off);
        acc.y += __shfl_xor_sync(0xffffffffu, acc.y, off);
        acc.z += __shfl_xor_sync(0xffffffffu, acc.z, off);
        acc.w += __shfl_xor_sync(0xffffffffu, acc.w, off);
    }

    if (slot == 0) {
        float inv = 1.f / ssum;
        float4* o4 = (float4*)(out + (size_t)gw * HD);
        o4[chunk] = make_float4(acc.x*inv, acc.y*inv, acc.z*inv, acc.w*inv);
    }
}

// ---------------- lin2 + log_softmax -----------------------------------------
__global__ void k_lin2(const float* __restrict__ w2, const float* __restrict__ b2,
                       float* __restrict__ out, int n) {
    __shared__ float ws[NC * HD];
    __shared__ float bs[NC];
    if (threadIdx.x < NC * HD) ws[threadIdx.x] = w2[threadIdx.x];
    if (threadIdx.x < NC)      bs[threadIdx.x] = b2[threadIdx.x];
    __syncthreads();
    int i = blockIdx.x * blockDim.x + threadIdx.x;
    if (i >= n) return;
    const float4* v4 = (const float4*)(g_h2 + (size_t)i * HD);
    float v[16];
    float4 t0 = v4[0], t1 = v4[1], t2 = v4[2], t3 = v4[3];
    v[0]=t0.x; v[1]=t0.y; v[2]=t0.z; v[3]=t0.w;
    v[4]=t1.x; v[5]=t1.y; v[6]=t1.z; v[7]=t1.w;
    v[8]=t2.x; v[9]=t2.y; v[10]=t2.z; v[11]=t2.w;
    v[12]=t3.x; v[13]=t3.y; v[14]=t3.z; v[15]=t3.w;
    float z[NC];
#pragma unroll
    for (int c = 0; c < NC; c++) {
        float s = bs[c];
#pragma unroll
        for (int k = 0; k < 16; k++) s += v[k] * ws[c * 16 + k];
        z[c] = s;
    }
    float mx = z[0];
#pragma unroll
    for (int c = 1; c < NC; c++) mx = fmaxf(mx, z[c]);
    float se = 0.f;
#pragma unroll
    for (int c = 0; c < NC; c++) se += __expf(z[c] - mx);
    float lse = mx + __logf(se);
#pragma unroll
    for (int c = 0; c < NC; c++) out[(size_t)i * NC + c] = z[c] - lse;
}

// ---------------- launch -----------------------------------------------------
extern "C" void kernel_launch(void* const* d_in, const int* in_sizes, int n_in,
                              void* d_out, int out_size) {
    const float* x    = (const float*)d_in[0];
    const int*   ei   = (const int*)  d_in[1];
    const float* w1   = (const float*)d_in[2];
    const float* b1   = (const float*)d_in[3];
    const float* bet2 = (const float*)d_in[4];
    const float* w2   = (const float*)d_in[5];
    const float* b2   = (const float*)d_in[6];
    float* out = (float*)d_out;

    int n = NN;
    int E = in_sizes[1] / 2;

    float* x1 = out + (size_t)n * NC;   // x1 output lives in d_out

    float* p_hn;  cudaGetSymbolAddress((void**)&p_hn,  g_hn);
    float* p_n1;  cudaGetSymbolAddress((void**)&p_n1,  g_nrm1);
    float* p_x1n; cudaGetSymbolAddress((void**)&p_x1n, g_x1n);
    float* p_n2;  cudaGetSymbolAddress((void**)&p_n2,  g_nrm2);
    float* p_h2;  cudaGetSymbolAddress((void**)&p_h2,  g_h2);

    const int T = 256;
    // CSR build
    k_deg_init<<<(n + T - 1) / T, T>>>(n);
    k_count<<<(E + T - 1) / T, T>>>(ei, E);
    int nchunk = (n + 1023) / 1024;
    k_scan_chunk<<<nchunk, 1024>>>(n);
    k_scan_aux<<<1, 128>>>(nchunk);
    k_scan_add<<<nchunk, 1024>>>(n);
    k_cursor_init<<<(n + T - 1) / T, T>>>(n);
    k_scatter<<<(E + n + T - 1) / T, T>>>(ei, E, n);

    // lin1 (+relu, +normalize)
    k_lin1<<<(n + 31) / 32, 256>>>(x, w1, b1, p_hn, p_n1, n);

    // conv1 (beta = 1) -> x1 directly into d_out
    int convBlocks = (n * 32 + 255) / 256;
    k_conv<<<convBlocks, 256>>>(p_hn, p_n1, nullptr, 1.0f, x1, n);

    // normalize x1, conv2 (beta = beta2)
    k_norm16<<<(n + T - 1) / T, T>>>(x1, p_x1n, p_n2, n);
    k_conv<<<convBlocks, 256>>>(p_x1n, p_n2, bet2, 1.0f, p_h2, n);

    // classifier + log_softmax
    k_lin2<<<(n + T - 1) / T, T>>>(w2, b2, out, n);
}

// round 3
// speedup vs baseline: 1.3571x; 1.0442x over previous
#include <cuda_runtime.h>
#include <math.h>

#define NN     100000
#define EE_MAX 3400000
#define HD     16
#define FIN    767
#define NC     10
#define EPSV   1e-12f

// ---------------- scratch ---------------------------------------------------
__device__ float g_hn  [NN * HD];   // normalized h
__device__ float g_nrm1[NN];        // max(||h||, eps)
__device__ float g_x1n [NN * HD];   // normalized x1
__device__ float g_nrm2[NN];        // max(||x1||, eps)
__device__ int   g_deg [NN];
__device__ int   g_rowptr[NN + 1];
__device__ int   g_cursor[NN];
__device__ int   g_csrc[EE_MAX];
__device__ int   g_aux[256];

// ---------------- f32x2 helpers ---------------------------------------------
__device__ __forceinline__ unsigned long long pk2(float lo, float hi) {
    unsigned long long r;
    asm("mov.b64 %0, {%1,%2};" : "=l"(r) : "f"(lo), "f"(hi));
    return r;
}
__device__ __forceinline__ void upk2(unsigned long long v, float& lo, float& hi) {
    asm("mov.b64 {%0,%1}, %2;" : "=f"(lo), "=f"(hi) : "l"(v));
}
__device__ __forceinline__ unsigned long long ffma2(unsigned long long a,
                                                    unsigned long long b,
                                                    unsigned long long c) {
    unsigned long long d;
    asm("fma.rn.f32x2 %0, %1, %2, %3;" : "=l"(d) : "l"(a), "l"(b), "l"(c));
    return d;
}
__device__ __forceinline__ unsigned long long fadd2(unsigned long long a,
                                                    unsigned long long b) {
    unsigned long long d;
    asm("add.rn.f32x2 %0, %1, %2;" : "=l"(d) : "l"(a), "l"(b));
    return d;
}

// ---------------- CSR build --------------------------------------------------
// counts edges AND self loops (idx >= E) ; g_deg pre-zeroed by memsetAsync
__global__ void k_count(const int* __restrict__ ei, int E, int n) {
    int idx = blockIdx.x * blockDim.x + threadIdx.x;
    if (idx < E) atomicAdd(&g_deg[__ldg(&ei[E + idx])], 1);
    else if (idx < E + n) atomicAdd(&g_deg[idx - E], 1);
}

// shfl-based inclusive scan over 512-element chunks
__global__ void k_scan_chunk(int n) {
    __shared__ int wsums[16];
    int tid = threadIdx.x, lane = tid & 31, w = tid >> 5;
    int gid = blockIdx.x * 512 + tid;
    int v = (gid < n) ? g_deg[gid] : 0;
    int s = v;
#pragma unroll
    for (int off = 1; off < 32; off <<= 1) {
        int t = __shfl_up_sync(0xffffffffu, s, off);
        if (lane >= off) s += t;
    }
    if (lane == 31) wsums[w] = s;
    __syncthreads();
    int add = 0;
#pragma unroll
    for (int i = 0; i < 16; i++) add += (i < w) ? wsums[i] : 0;
    s += add;
    if (gid < n) g_rowptr[gid + 1] = s;
    if (tid == 511) g_aux[blockIdx.x] = s;
}

// exclusive scan of g_aux (nb <= 256), 256 threads
__global__ void k_scan_aux(int nb) {
    int tid = threadIdx.x, lane = tid & 31, w = tid >> 5;
    int v = (tid < nb) ? g_aux[tid] : 0;
    int s = v;
#pragma unroll
    for (int off = 1; off < 32; off <<= 1) {
        int t = __shfl_up_sync(0xffffffffu, s, off);
        if (lane >= off) s += t;
    }
    __shared__ int wsum[8];
    if (lane == 31) wsum[w] = s;
    __syncthreads();
    int add = 0;
#pragma unroll
    for (int i = 0; i < 8; i++) add += (i < w) ? wsum[i] : 0;
    if (tid < nb) g_aux[tid] = s - v + add;   // exclusive
}

// add chunk offsets; also materialize cursor = rowptr (exclusive)
__global__ void k_scan_add(int n) {
    int gid = blockIdx.x * 512 + threadIdx.x;
    if (gid < n) {
        int v = g_rowptr[gid + 1] + g_aux[blockIdx.x];
        g_rowptr[gid + 1] = v;
        if (gid + 1 < n) g_cursor[gid + 1] = v;
    }
    if (gid == 0) { g_rowptr[0] = 0; g_cursor[0] = 0; }
}

__global__ void k_scatter(const int* __restrict__ ei, int E, int n) {
    int idx = blockIdx.x * blockDim.x + threadIdx.x;
    int total = E + n;
    if (idx >= total) return;
    int src, dst;
    if (idx < E) { src = __ldg(&ei[idx]); dst = __ldg(&ei[E + idx]); }
    else         { src = idx - E; dst = src; }
    int pos = atomicAdd(&g_cursor[dst], 1);
    g_csrc[pos] = src;
}

// ---------------- lin1 + relu + row-normalize (f32x2 packed) -----------------
__global__ __launch_bounds__(256) void k_lin1(const float* __restrict__ x,
                                              const float* __restrict__ w,
                                              const float* __restrict__ b,
                                              float* __restrict__ hn,
                                              float* __restrict__ nrm,
                                              int n) {
    __shared__ unsigned long long wt2[HD * 384];   // 48KB packed weights
    {
        float* wf = (float*)wt2;
        for (int o = threadIdx.x; o < HD * 768; o += 256) {
            int k = o / 768;
            int j = o - k * 768;
            wf[o] = (j < FIN) ? w[k * FIN + j] : 0.f;
        }
    }
    __syncthreads();

    int warp = threadIdx.x >> 5, lane = threadIdx.x & 31;
    int rowBase = (blockIdx.x * 8 + warp) * 4;
    if (rowBase >= n) return;

    unsigned long long acc[64];
#pragma unroll
    for (int i = 0; i < 64; i++) acc[i] = 0ull;

    const float* x0 = x + (size_t)rowBase * FIN;

    unsigned long long xv[4];
    {
        int jj = lane * 2;
#pragma unroll
        for (int r = 0; r < 4; r++) {
            const float* xr = x0 + r * FIN;
            float lo = xr[jj];
            float hi = (jj == 766 && (rowBase + r) == n - 1) ? 0.f : xr[jj + 1];
            xv[r] = pk2(lo, hi);
        }
    }

    for (int it = 0; it < 12; ++it) {
        int jp = lane + it * 32;
        unsigned long long xnv[4];
        if (it + 1 < 12) {
            int jj = (jp + 32) * 2;
#pragma unroll
            for (int r = 0; r < 4; r++) {
                const float* xr = x0 + r * FIN;
                float lo = xr[jj];
                float hi = (jj == 766 && (rowBase + r) == n - 1) ? 0.f : xr[jj + 1];
                xnv[r] = pk2(lo, hi);
            }
        }
#pragma unroll
        for (int k = 0; k < HD; k++) {
            unsigned long long wv = wt2[k * 384 + jp];
            acc[0 * 16 + k] = ffma2(xv[0], wv, acc[0 * 16 + k]);
            acc[1 * 16 + k] = ffma2(xv[1], wv, acc[1 * 16 + k]);
            acc[2 * 16 + k] = ffma2(xv[2], wv, acc[2 * 16 + k]);
            acc[3 * 16 + k] = ffma2(xv[3], wv, acc[3 * 16 + k]);
        }
        if (it + 1 < 12) {
#pragma unroll
            for (int r = 0; r < 4; r++) xv[r] = xnv[r];
        }
    }

#define REDSTEP(OFF, HALF)                                                     \
    {                                                                          \
        bool up = (lane & OFF) != 0;                                           \
        _Pragma("unroll")                                                      \
        for (int i = 0; i < HALF; i++) {                                       \
            unsigned long long send = up ? acc[i] : acc[i + HALF];             \
            unsigned long long recv = __shfl_xor_sync(0xffffffffu, send, OFF); \
            unsigned long long keep = up ? acc[i + HALF] : acc[i];             \
            acc[i] = fadd2(keep, recv);                                        \
        }                                                                      \
    }
    REDSTEP(16, 32)
    REDSTEP(8, 16)
    REDSTEP(4, 8)
    REDSTEP(2, 4)
    REDSTEP(1, 2)
#undef REDSTEP

    int r  = lane >> 3;
    int kk = (lane & 7) * 2;
    float a0, a1, b0, b1;
    upk2(acc[0], a0, a1);
    upk2(acc[1], b0, b1);
    float h0 = fmaxf(a0 + a1 + __ldg(b + kk),     0.f);
    float h1 = fmaxf(b0 + b1 + __ldg(b + kk + 1), 0.f);
    float ss = h0 * h0 + h1 * h1;
    ss += __shfl_xor_sync(0xffffffffu, ss, 1);
    ss += __shfl_xor_sync(0xffffffffu, ss, 2);
    ss += __shfl_xor_sync(0xffffffffu, ss, 4);
    float nr  = fmaxf(sqrtf(ss), EPSV);
    float inv = 1.f / nr;
    int row = rowBase + r;
    float2 o; o.x = h0 * inv; o.y = h1 * inv;
    *(float2*)(hn + (size_t)row * HD + kk) = o;
    if ((lane & 7) == 0) nrm[row] = nr;
}

// ---------------- AGNN conv (warp/node, quad/edge, pipelined) ----------------
// MODE 0: out=x1 (raw), outn=normalized x1, nrmout=||x1||  (fused norm16)
// MODE 1: out=log_softmax(lin2(h2))                        (fused lin2)
template <int MODE>
__global__ __launch_bounds__(256) void k_conv(const float* __restrict__ featn,
                                              const float* __restrict__ nrm,
                                              const float* __restrict__ beta_ptr,
                                              float* __restrict__ out,
                                              float* __restrict__ outn,
                                              float* __restrict__ nrmout,
                                              const float* __restrict__ w2,
                                              const float* __restrict__ b2,
                                              int n) {
    __shared__ float ws[NC * HD + NC];
    if (MODE == 1) {
        if (threadIdx.x < NC * HD) ws[threadIdx.x] = w2[threadIdx.x];
        if (threadIdx.x < NC)      ws[NC * HD + threadIdx.x] = b2[threadIdx.x];
        __syncthreads();
    }

    int gw    = (blockIdx.x * blockDim.x + threadIdx.x) >> 5;
    int lane  = threadIdx.x & 31;
    if (gw >= n) return;
    int chunk = lane & 3;
    int slot  = lane >> 2;

    float beta = (MODE == 1) ? __ldg(beta_ptr) : 1.0f;
    float ab   = fabsf(beta);

    const float4* fn4 = (const float4*)featn;
    float4 q = fn4[(size_t)gw * 4 + chunk];
    q.x *= beta; q.y *= beta; q.z *= beta; q.w *= beta;

    int start = g_rowptr[gw], end = g_rowptr[gw + 1];
    int nit = (end - start + 7) >> 3;

    float ssum = 0.f;
    float4 acc = make_float4(0.f, 0.f, 0.f, 0.f);

    int e = start + slot;
    bool valid = (e < end);
    int s = valid ? __ldg(&g_csrc[e]) : 0;

    for (int it = 0; it < nit; ++it) {
        int  en = e + 8;
        bool vn = (en < end);
        int  sn = vn ? __ldg(&g_csrc[en]) : 0;        // prefetch next index
        float nv = __ldg(&nrm[s]);                    // issue before shfl chain
        float4 v = fn4[(size_t)s * 4 + chunk];
        float d = v.x*q.x + v.y*q.y + v.z*q.z + v.w*q.w;
        d += __shfl_xor_sync(0xffffffffu, d, 1);
        d += __shfl_xor_sync(0xffffffffu, d, 2);
        float ex  = valid ? __expf(d - ab) : 0.f;
        float exn = ex * nv;
        ssum += ex;
        acc.x += exn * v.x; acc.y += exn * v.y;
        acc.z += exn * v.z; acc.w += exn * v.w;
        e = en; s = sn; valid = vn;
    }

#pragma unroll
    for (int off = 4; off <= 16; off <<= 1) {
        ssum  += __shfl_xor_sync(0xffffffffu, ssum,  off);
        acc.x += __shfl_xor_sync(0xffffffffu, acc.x, off);
        acc.y += __shfl_xor_sync(0xffffffffu, acc.y, off);
        acc.z += __shfl_xor_sync(0xffffffffu, acc.z, off);
        acc.w += __shfl_xor_sync(0xffffffffu, acc.w, off);
    }
    // all 32 lanes now hold full (ssum, acc-for-their-chunk)
    float inv = 1.f / ssum;
    float4 o = make_float4(acc.x*inv, acc.y*inv, acc.z*inv, acc.w*inv);

    if (MODE == 0) {
        float ss = o.x*o.x + o.y*o.y + o.z*o.z + o.w*o.w;
        ss += __shfl_xor_sync(0xffffffffu, ss, 1);
        ss += __shfl_xor_sync(0xffffffffu, ss, 2);
        float nr   = fmaxf(sqrtf(ss), EPSV);
        float invn = 1.f / nr;
        if (slot == 0) {
            ((float4*)out )[(size_t)gw * 4 + chunk] = o;
            ((float4*)outn)[(size_t)gw * 4 + chunk] =
                make_float4(o.x*invn, o.y*invn, o.z*invn, o.w*invn);
            if (lane == 0) nrmout[gw] = nr;
        }
    } else {
        float z[NC];
#pragma unroll
        for (int c = 0; c < NC; c++) {
            const float* wc = ws + c * HD + chunk * 4;
            z[c] = o.x*wc[0] + o.y*wc[1] + o.z*wc[2] + o.w*wc[3];
        }
#pragma unroll
        for (int off = 1; off <= 2; off <<= 1)
#pragma unroll
            for (int c = 0; c < NC; c++)
                z[c] += __shfl_xor_sync(0xffffffffu, z[c], off);
#pragma unroll
        for (int c = 0; c < NC; c++) z[c] += ws[NC * HD + c];
        float mx = z[0];
#pragma unroll
        for (int c = 1; c < NC; c++) mx = fmaxf(mx, z[c]);
        float se = 0.f;
#pragma unroll
        for (int c = 0; c < NC; c++) se += __expf(z[c] - mx);
        float lse = mx + __logf(se);
        if (lane < NC) out[(size_t)gw * NC + lane] = z[lane] - lse;
    }
}

// ---------------- launch -----------------------------------------------------
extern "C" void kernel_launch(void* const* d_in, const int* in_sizes, int n_in,
                              void* d_out, int out_size) {
    const float* x    = (const float*)d_in[0];
    const int*   ei   = (const int*)  d_in[1];
    const float* w1   = (const float*)d_in[2];
    const float* b1   = (const float*)d_in[3];
    const float* bet2 = (const float*)d_in[4];
    const float* w2   = (const float*)d_in[5];
    const float* b2   = (const float*)d_in[6];
    float* out = (float*)d_out;

    int n = NN;
    int E = in_sizes[1] / 2;

    float* x1 = out + (size_t)n * NC;   // x1 output lives in d_out tail

    float* p_hn;  cudaGetSymbolAddress((void**)&p_hn,  g_hn);
    float* p_n1;  cudaGetSymbolAddress((void**)&p_n1,  g_nrm1);
    float* p_x1n; cudaGetSymbolAddress((void**)&p_x1n, g_x1n);
    float* p_n2;  cudaGetSymbolAddress((void**)&p_n2,  g_nrm2);
    int*   p_deg; cudaGetSymbolAddress((void**)&p_deg, g_deg);

    static cudaStream_t s2 = nullptr;
    static cudaEvent_t evFork = nullptr, evJoin = nullptr;
    if (!s2) {
        cudaStreamCreateWithFlags(&s2, cudaStreamNonBlocking);
        cudaEventCreateWithFlags(&evFork, cudaEventDisableTiming);
        cudaEventCreateWithFlags(&evJoin, cudaEventDisableTiming);
    }

    const int T = 256;
    int nchunk = (n + 511) / 512;

    // ---- fork: CSR build on s2, lin1 on default stream ----
    cudaEventRecord(evFork, 0);
    cudaStreamWaitEvent(s2, evFork, 0);

    cudaMemsetAsync(p_deg, 0, n * sizeof(int), s2);
    k_count<<<(E + n + T - 1) / T, T, 0, s2>>>(ei, E, n);
    k_scan_chunk<<<nchunk, 512, 0, s2>>>(n);
    k_scan_aux<<<1, 256, 0, s2>>>(nchunk);

    k_lin1<<<(n + 31) / 32, 256>>>(x, w1, b1, p_hn, p_n1, n);   // default stream

    k_scan_add<<<nchunk, 512, 0, s2>>>(n);
    k_scatter<<<(E + n + T - 1) / T, T, 0, s2>>>(ei, E, n);

    // ---- join ----
    cudaEventRecord(evJoin, s2);
    cudaStreamWaitEvent(0, evJoin, 0);

    int convBlocks = (n * 32 + 255) / 256;
    // conv1: beta=1, writes x1 (d_out), x1n, nrm2; norm fused
    k_conv<0><<<convBlocks, 256>>>(p_hn, p_n1, nullptr, x1, p_x1n, p_n2,
                                   nullptr, nullptr, n);
    // conv2: beta=beta2, lin2 + log_softmax fused, writes logits
    k_conv<1><<<convBlocks, 256>>>(p_x1n, p_n2, bet2, out, nullptr, nullptr,
                                   w2, b2, n);
}

// round 4
// speedup vs baseline: 1.9757x; 1.4559x over previous
#include <cuda_runtime.h>
#include <math.h>

#define NN     100000
#define EE_MAX 3400000
#define HD     16
#define FIN    767
#define NC     10
#define EPSV   1e-12f

// ---------------- scratch ---------------------------------------------------
__device__ float g_hn  [NN * HD];   // normalized h
__device__ float g_nrm1[NN];        // max(||h||, eps)
__device__ float g_x1n [NN * HD];   // normalized x1
__device__ float g_nrm2[NN];        // max(||x1||, eps)
__device__ int   g_deg [NN];
__device__ int   g_rowptr[NN + 1];
__device__ int   g_cursor[NN];
__device__ int   g_csrc[EE_MAX];
__device__ int   g_aux[256];

// ---------------- f32x2 helpers ---------------------------------------------
__device__ __forceinline__ unsigned long long pk2(float lo, float hi) {
    unsigned long long r;
    asm("mov.b64 %0, {%1,%2};" : "=l"(r) : "f"(lo), "f"(hi));
    return r;
}
__device__ __forceinline__ void upk2(unsigned long long v, float& lo, float& hi) {
    asm("mov.b64 {%0,%1}, %2;" : "=f"(lo), "=f"(hi) : "l"(v));
}
__device__ __forceinline__ unsigned long long ffma2(unsigned long long a,
                                                    unsigned long long b,
                                                    unsigned long long c) {
    unsigned long long d;
    asm("fma.rn.f32x2 %0, %1, %2, %3;" : "=l"(d) : "l"(a), "l"(b), "l"(c));
    return d;
}
__device__ __forceinline__ unsigned long long fadd2(unsigned long long a,
                                                    unsigned long long b) {
    unsigned long long d;
    asm("add.rn.f32x2 %0, %1, %2;" : "=l"(d) : "l"(a), "l"(b));
    return d;
}

// ---------------- CSR build --------------------------------------------------
__global__ void k_count(const int* __restrict__ ei, int E, int n) {
    int idx = blockIdx.x * blockDim.x + threadIdx.x;
    if (idx < E) atomicAdd(&g_deg[__ldg(&ei[E + idx])], 1);
    else if (idx < E + n) atomicAdd(&g_deg[idx - E], 1);
}

__global__ void k_scan_chunk(int n) {
    __shared__ int wsums[16];
    int tid = threadIdx.x, lane = tid & 31, w = tid >> 5;
    int gid = blockIdx.x * 512 + tid;
    int v = (gid < n) ? g_deg[gid] : 0;
    int s = v;
#pragma unroll
    for (int off = 1; off < 32; off <<= 1) {
        int t = __shfl_up_sync(0xffffffffu, s, off);
        if (lane >= off) s += t;
    }
    if (lane == 31) wsums[w] = s;
    __syncthreads();
    int add = 0;
#pragma unroll
    for (int i = 0; i < 16; i++) add += (i < w) ? wsums[i] : 0;
    s += add;
    if (gid < n) g_rowptr[gid + 1] = s;
    if (tid == 511) g_aux[blockIdx.x] = s;
}

__global__ void k_scan_aux(int nb) {
    int tid = threadIdx.x, lane = tid & 31, w = tid >> 5;
    int v = (tid < nb) ? g_aux[tid] : 0;
    int s = v;
#pragma unroll
    for (int off = 1; off < 32; off <<= 1) {
        int t = __shfl_up_sync(0xffffffffu, s, off);
        if (lane >= off) s += t;
    }
    __shared__ int wsum[8];
    if (lane == 31) wsum[w] = s;
    __syncthreads();
    int add = 0;
#pragma unroll
    for (int i = 0; i < 8; i++) add += (i < w) ? wsum[i] : 0;
    if (tid < nb) g_aux[tid] = s - v + add;   // exclusive
}

__global__ void k_scan_add(int n) {
    int gid = blockIdx.x * 512 + threadIdx.x;
    if (gid < n) {
        int v = g_rowptr[gid + 1] + g_aux[blockIdx.x];
        g_rowptr[gid + 1] = v;
        if (gid + 1 < n) g_cursor[gid + 1] = v;
    }
    if (gid == 0) { g_rowptr[0] = 0; g_cursor[0] = 0; }
}

__global__ void k_scatter(const int* __restrict__ ei, int E, int n) {
    int idx = blockIdx.x * blockDim.x + threadIdx.x;
    int total = E + n;
    if (idx >= total) return;
    int src, dst;
    if (idx < E) { src = __ldg(&ei[idx]); dst = __ldg(&ei[E + idx]); }
    else         { src = idx - E; dst = src; }
    int pos = atomicAdd(&g_cursor[dst], 1);
    g_csrc[pos] = src;
}

// ---------------- lin1: K-packed f32x2, conflict-free LDS.128 ----------------
// warp = 4 rows. lane = j-pair slice. acc[r*8+kp] = f32x2 outputs (2kp,2kp+1).
// smem quad (jp,kp): [w[2kp][2jp], w[2kp+1][2jp], w[2kp][2jp+1], w[2kp+1][2jp+1]]
// float offset F(jp,kp) = jp*36 + kp*4 (144B row stride -> no bank conflicts)
#define LIN1_SMEM_BYTES (384 * 36 * 4)   // 55296
__global__ __launch_bounds__(256, 2) void k_lin1(const float* __restrict__ x,
                                                 const float* __restrict__ w,
                                                 const float* __restrict__ b,
                                                 float* __restrict__ hn,
                                                 float* __restrict__ nrm,
                                                 int n) {
    extern __shared__ float wf[];
    // stage weights, K-pair-packed
    for (int q = threadIdx.x; q < 384 * 8; q += 256) {
        int jp = q >> 3, kp = q & 7;
        int j = 2 * jp, k = 2 * kp;
        float f0 = w[k * FIN + j];
        float f1 = w[(k + 1) * FIN + j];
        float f2 = (j + 1 < FIN) ? w[k * FIN + j + 1] : 0.f;
        float f3 = (j + 1 < FIN) ? w[(k + 1) * FIN + j + 1] : 0.f;
        *(float4*)(wf + jp * 36 + kp * 4) = make_float4(f0, f1, f2, f3);
    }
    __syncthreads();

    int warp = threadIdx.x >> 5, lane = threadIdx.x & 31;
    int rowBase = (blockIdx.x * 8 + warp) * 4;
    if (rowBase >= n) return;
    bool tailWarp = (rowBase + 4 >= n);

    unsigned long long acc[32];
#pragma unroll
    for (int i = 0; i < 32; i++) acc[i] = 0ull;

    const float* x0 = x + (size_t)rowBase * FIN;

    for (int it = 0; it < 12; ++it) {
        int jp = lane + it * 32;
        int j  = 2 * jp;
        unsigned long long alo[4], ahi[4];
#pragma unroll
        for (int r = 0; r < 4; r++) {
            const float* xr = x0 + r * FIN;
            float lo = xr[j];
            float hi = (tailWarp && jp == 383 && (rowBase + r) == n - 1)
                           ? 0.f : xr[j + 1];
            alo[r] = pk2(lo, lo);
            ahi[r] = pk2(hi, hi);
        }
#pragma unroll
        for (int kp = 0; kp < 8; kp++) {
            ulonglong2 wq = *(const ulonglong2*)(wf + jp * 36 + kp * 4);
#pragma unroll
            for (int r = 0; r < 4; r++) {
                unsigned long long a = acc[r * 8 + kp];
                a = ffma2(alo[r], wq.x, a);
                a = ffma2(ahi[r], wq.y, a);
                acc[r * 8 + kp] = a;
            }
        }
    }

    // halving butterfly: lane L ends owning acc index c == L
#define REDSTEP(OFF, HALF)                                                     \
    {                                                                          \
        bool up = (lane & OFF) != 0;                                           \
        _Pragma("unroll")                                                      \
        for (int i = 0; i < HALF; i++) {                                       \
            unsigned long long send = up ? acc[i] : acc[i + HALF];             \
            unsigned long long recv = __shfl_xor_sync(0xffffffffu, send, OFF); \
            unsigned long long keep = up ? acc[i + HALF] : acc[i];             \
            acc[i] = fadd2(keep, recv);                                        \
        }                                                                      \
    }
    REDSTEP(16, 16)
    REDSTEP(8, 8)
    REDSTEP(4, 4)
    REDSTEP(2, 2)
    REDSTEP(1, 1)
#undef REDSTEP

    // lane owns outputs (2kp, 2kp+1) of row rowBase + r;  r=lane>>3, kp=lane&7
    int r  = lane >> 3;
    int kk = (lane & 7) * 2;
    float h0, h1;
    upk2(acc[0], h0, h1);
    h0 = fmaxf(h0 + __ldg(b + kk),     0.f);
    h1 = fmaxf(h1 + __ldg(b + kk + 1), 0.f);
    float ss = h0 * h0 + h1 * h1;
    ss += __shfl_xor_sync(0xffffffffu, ss, 1);
    ss += __shfl_xor_sync(0xffffffffu, ss, 2);
    ss += __shfl_xor_sync(0xffffffffu, ss, 4);
    float nr  = fmaxf(sqrtf(ss), EPSV);
    float inv = 1.f / nr;
    int row = rowBase + r;
    float2 o; o.x = h0 * inv; o.y = h1 * inv;
    *(float2*)(hn + (size_t)row * HD + kk) = o;
    if ((lane & 7) == 0) nrm[row] = nr;
}

// ---------------- AGNN conv (warp/node, quad/edge, pipelined) ----------------
template <int MODE>
__global__ __launch_bounds__(256) void k_conv(const float* __restrict__ featn,
                                              const float* __restrict__ nrm,
                                              const float* __restrict__ beta_ptr,
                                              float* __restrict__ out,
                                              float* __restrict__ outn,
                                              float* __restrict__ nrmout,
                                              const float* __restrict__ w2,
                                              const float* __restrict__ b2,
                                              int n) {
    __shared__ float ws[NC * HD + NC];
    if (MODE == 1) {
        if (threadIdx.x < NC * HD) ws[threadIdx.x] = w2[threadIdx.x];
        if (threadIdx.x < NC)      ws[NC * HD + threadIdx.x] = b2[threadIdx.x];
        __syncthreads();
    }

    int gw    = (blockIdx.x * blockDim.x + threadIdx.x) >> 5;
    int lane  = threadIdx.x & 31;
    if (gw >= n) return;
    int chunk = lane & 3;
    int slot  = lane >> 2;

    float beta = (MODE == 1) ? __ldg(beta_ptr) : 1.0f;
    float ab   = fabsf(beta);

    const float4* fn4 = (const float4*)featn;
    float4 q = fn4[(size_t)gw * 4 + chunk];
    q.x *= beta; q.y *= beta; q.z *= beta; q.w *= beta;

    int start = g_rowptr[gw], end = g_rowptr[gw + 1];
    int nit = (end - start + 7) >> 3;

    float ssum = 0.f;
    float4 acc = make_float4(0.f, 0.f, 0.f, 0.f);

    int e = start + slot;
    bool valid = (e < end);
    int s = valid ? __ldg(&g_csrc[e]) : 0;

    for (int it = 0; it < nit; ++it) {
        int  en = e + 8;
        bool vn = (en < end);
        int  sn = vn ? __ldg(&g_csrc[en]) : 0;
        float nv = __ldg(&nrm[s]);
        float4 v = fn4[(size_t)s * 4 + chunk];
        float d = v.x*q.x + v.y*q.y + v.z*q.z + v.w*q.w;
        d += __shfl_xor_sync(0xffffffffu, d, 1);
        d += __shfl_xor_sync(0xffffffffu, d, 2);
        float ex  = valid ? __expf(d - ab) : 0.f;
        float exn = ex * nv;
        ssum += ex;
        acc.x += exn * v.x; acc.y += exn * v.y;
        acc.z += exn * v.z; acc.w += exn * v.w;
        e = en; s = sn; valid = vn;
    }

#pragma unroll
    for (int off = 4; off <= 16; off <<= 1) {
        ssum  += __shfl_xor_sync(0xffffffffu, ssum,  off);
        acc.x += __shfl_xor_sync(0xffffffffu, acc.x, off);
        acc.y += __shfl_xor_sync(0xffffffffu, acc.y, off);
        acc.z += __shfl_xor_sync(0xffffffffu, acc.z, off);
        acc.w += __shfl_xor_sync(0xffffffffu, acc.w, off);
    }
    float inv = 1.f / ssum;
    float4 o = make_float4(acc.x*inv, acc.y*inv, acc.z*inv, acc.w*inv);

    if (MODE == 0) {
        float ss = o.x*o.x + o.y*o.y + o.z*o.z + o.w*o.w;
        ss += __shfl_xor_sync(0xffffffffu, ss, 1);
        ss += __shfl_xor_sync(0xffffffffu, ss, 2);
        float nr   = fmaxf(sqrtf(ss), EPSV);
        float invn = 1.f / nr;
        if (slot == 0) {
            ((float4*)out )[(size_t)gw * 4 + chunk] = o;
            ((float4*)outn)[(size_t)gw * 4 + chunk] =
                make_float4(o.x*invn, o.y*invn, o.z*invn, o.w*invn);
            if (lane == 0) nrmout[gw] = nr;
        }
    } else {
        float z[NC];
#pragma unroll
        for (int c = 0; c < NC; c++) {
            const float* wc = ws + c * HD + chunk * 4;
            z[c] = o.x*wc[0] + o.y*wc[1] + o.z*wc[2] + o.w*wc[3];
        }
#pragma unroll
        for (int off = 1; off <= 2; off <<= 1)
#pragma unroll
            for (int c = 0; c < NC; c++)
                z[c] += __shfl_xor_sync(0xffffffffu, z[c], off);
#pragma unroll
        for (int c = 0; c < NC; c++) z[c] += ws[NC * HD + c];
        float mx = z[0];
#pragma unroll
        for (int c = 1; c < NC; c++) mx = fmaxf(mx, z[c]);
        float se = 0.f;
#pragma unroll
        for (int c = 0; c < NC; c++) se += __expf(z[c] - mx);
        float lse = mx + __logf(se);
        if (lane < NC) out[(size_t)gw * NC + lane] = z[lane] - lse;
    }
}

// ---------------- launch -----------------------------------------------------
extern "C" void kernel_launch(void* const* d_in, const int* in_sizes, int n_in,
                              void* d_out, int out_size) {
    const float* x    = (const float*)d_in[0];
    const int*   ei   = (const int*)  d_in[1];
    const float* w1   = (const float*)d_in[2];
    const float* b1   = (const float*)d_in[3];
    const float* bet2 = (const float*)d_in[4];
    const float* w2   = (const float*)d_in[5];
    const float* b2   = (const float*)d_in[6];
    float* out = (float*)d_out;

    int n = NN;
    int E = in_sizes[1] / 2;

    float* x1 = out + (size_t)n * NC;   // x1 output lives in d_out tail

    float* p_hn;  cudaGetSymbolAddress((void**)&p_hn,  g_hn);
    float* p_n1;  cudaGetSymbolAddress((void**)&p_n1,  g_nrm1);
    float* p_x1n; cudaGetSymbolAddress((void**)&p_x1n, g_x1n);
    float* p_n2;  cudaGetSymbolAddress((void**)&p_n2,  g_nrm2);
    int*   p_deg; cudaGetSymbolAddress((void**)&p_deg, g_deg);

    static cudaStream_t s2 = nullptr;
    static cudaEvent_t evFork = nullptr, evJoin = nullptr;
    if (!s2) {
        cudaStreamCreateWithFlags(&s2, cudaStreamNonBlocking);
        cudaEventCreateWithFlags(&evFork, cudaEventDisableTiming);
        cudaEventCreateWithFlags(&evJoin, cudaEventDisableTiming);
        cudaFuncSetAttribute(k_lin1, cudaFuncAttributeMaxDynamicSharedMemorySize,
                             LIN1_SMEM_BYTES);
    }

    const int T = 256;
    int nchunk = (n + 511) / 512;

    // ---- fork: CSR build on s2, lin1 on default stream ----
    cudaEventRecord(evFork, 0);
    cudaStreamWaitEvent(s2, evFork, 0);

    cudaMemsetAsync(p_deg, 0, n * sizeof(int), s2);
    k_count<<<(E + n + T - 1) / T, T, 0, s2>>>(ei, E, n);
    k_scan_chunk<<<nchunk, 512, 0, s2>>>(n);
    k_scan_aux<<<1, 256, 0, s2>>>(nchunk);

    k_lin1<<<(n + 31) / 32, 256, LIN1_SMEM_BYTES>>>(x, w1, b1, p_hn, p_n1, n);

    k_scan_add<<<nchunk, 512, 0, s2>>>(n);
    k_scatter<<<(E + n + T - 1) / T, T, 0, s2>>>(ei, E, n);

    // ---- join ----
    cudaEventRecord(evJoin, s2);
    cudaStreamWaitEvent(0, evJoin, 0);

    int convBlocks = (n * 32 + 255) / 256;
    k_conv<0><<<convBlocks, 256>>>(p_hn, p_n1, nullptr, x1, p_x1n, p_n2,
                                   nullptr, nullptr, n);
    k_conv<1><<<convBlocks, 256>>>(p_x1n, p_n2, bet2, out, nullptr, nullptr,
                                   w2, b2, n);
}